// round 13
// baseline (speedup 1.0000x reference)
#include <cuda_runtime.h>
#include <cuda_fp16.h>
#include <cstdint>

// B=8192, D=256, categories int32 on the wire.
#define BDIM 8192
#define DDIM 256
#define INV_T 1.4285714285714286f
#define M0    1.4285714285714286f
#define C1    2.0609929155f          // INV_T * log2(e)
#define C2    2.0609929155f          // M0 * log2(e)
#define LN2   0.69314718056f

#define BM 128
#define NBLK 64
#define THREADS 512                  // 16 warps: 4 in M x 4 in N
#define GRID_MMA 148

#define TILEB 65536                  // 128 rows x 512 B (XOR-swizzled tile image)
#define TILE_HALF 32768
#define A_OFF   0
#define B_OFF   TILEB                // two B buffers
#define CAT_OFF (3 * TILEB)          // int[3][128] (triple-buffered)
#define RED_OFF (CAT_OFF + 1536)     // 8 KB shared reduction scratch
#define MBAR_OFF (RED_OFF + 8192)
#define SMEM_NEED (MBAR_OFF + 64)

#define SLOTS (NBLK * BDIM)
#define MERGE_BLKS 512

__device__ __half g_normh[BDIM * DDIM];
__device__ float  g_pos [SLOTS];
__device__ float  g_negs[SLOTS];
__device__ float  g_psum[MERGE_BLKS];
__device__ float  g_pcnt[MERGE_BLKS];
__device__ int    g_sem;             // zero-init; self-resetting

// ---------------- helpers ----------------
__device__ __forceinline__ uint32_t smem_u32(const void* p) {
    uint32_t a;
    asm("{ .reg .u64 t; cvta.to.shared.u64 t, %1; cvt.u32.u64 %0, t; }" : "=r"(a) : "l"(p));
    return a;
}
__device__ __forceinline__ float ex2f(float x) {
    float y;
    asm("ex2.approx.ftz.f32 %0, %1;" : "=f"(y) : "f"(x));
    return y;
}
__device__ __forceinline__ void mbar_init(uint32_t mbar, uint32_t cnt) {
    asm volatile("mbarrier.init.shared.b64 [%0], %1;" :: "r"(mbar), "r"(cnt) : "memory");
}
__device__ __forceinline__ void mbar_expect_tx(uint32_t mbar, uint32_t bytes) {
    asm volatile("mbarrier.arrive.expect_tx.shared.b64 _, [%0], %1;"
                 :: "r"(mbar), "r"(bytes) : "memory");
}
__device__ __forceinline__ void mbar_wait(uint32_t mbar, uint32_t parity) {
    asm volatile(
        "{\n\t.reg .pred P;\n\t"
        "WL_%=:\n\t"
        "mbarrier.try_wait.parity.acquire.cta.shared::cta.b64 P, [%0], %1, 0x989680;\n\t"
        "@P bra.uni WD_%=;\n\t"
        "bra.uni WL_%=;\n\t"
        "WD_%=:\n\t}"
        :: "r"(mbar), "r"(parity) : "memory");
}
__device__ __forceinline__ void bulk_cp(uint32_t dst, const void* src, uint32_t bytes,
                                        uint32_t mbar) {
    asm volatile(
        "cp.async.bulk.shared::cta.global.mbarrier::complete_tx::bytes [%0], [%1], %2, [%3];"
        :: "r"(dst), "l"(src), "r"(bytes), "r"(mbar) : "memory");
}
__device__ __forceinline__ void ldm4(uint32_t r[4], uint32_t addr) {
    asm volatile("ldmatrix.sync.aligned.m8n8.x4.shared.b16 {%0,%1,%2,%3}, [%4];"
                 : "=r"(r[0]), "=r"(r[1]), "=r"(r[2]), "=r"(r[3]) : "r"(addr));
}
__device__ __forceinline__ void mma16816(float d[4], const uint32_t a[4],
                                         uint32_t b0, uint32_t b1) {
    asm volatile(
        "mma.sync.aligned.m16n8k16.row.col.f32.f16.f16.f32 "
        "{%0,%1,%2,%3},{%4,%5,%6,%7},{%8,%9},{%0,%1,%2,%3};\n"
        : "+f"(d[0]), "+f"(d[1]), "+f"(d[2]), "+f"(d[3])
        : "r"(a[0]), "r"(a[1]), "r"(a[2]), "r"(a[3]), "r"(b0), "r"(b1));
}
__device__ __forceinline__ void tile_of(int k, int& it, int& jt) {
    int p = k / 65;
    int q = k - p * 65;
    int n1 = NBLK - p;
    if (q < n1) { it = p;            jt = p + q; }
    else        { it = NBLK - 1 - p; jt = (NBLK - 1 - p) + (q - n1); }
}

// ---- tile MMA: zero acc, 16 k-chunks of ldmatrix + mma ----
__device__ __forceinline__ void do_mma(float (&acc)[2][4][4],
                                       const uint32_t aRow[2], uint32_t bBuf,
                                       const uint32_t bRow[2],
                                       int gh, int gl, int r7) {
    #pragma unroll
    for (int mf = 0; mf < 2; mf++)
        #pragma unroll
        for (int nf = 0; nf < 4; nf++)
            #pragma unroll
            for (int c = 0; c < 4; c++) acc[mf][nf][c] = 0.0f;
    #pragma unroll
    for (int kc = 0; kc < 16; kc++) {
        const int ca = kc * 2 + gh;
        const int cb = kc * 2 + gl;
        const uint32_t swa = (uint32_t)(((ca & 24) | ((ca ^ r7) & 7)) << 4);
        const uint32_t swb = (uint32_t)(((cb & 24) | ((cb ^ r7) & 7)) << 4);
        uint32_t af[2][4], bf[2][4];
        ldm4(af[0], aRow[0] + swa);
        ldm4(af[1], aRow[1] + swa);
        ldm4(bf[0], bBuf + bRow[0] + swb);
        ldm4(bf[1], bBuf + bRow[1] + swb);
        #pragma unroll
        for (int mf = 0; mf < 2; mf++)
            #pragma unroll
            for (int nf = 0; nf < 4; nf++)
                mma16816(acc[mf][nf], af[mf],
                         bf[nf >> 1][(nf & 1) * 2], bf[nf >> 1][(nf & 1) * 2 + 1]);
    }
}

// ---- deferred epilogue compute for the PREVIOUS tile's accumulators ----
__device__ __forceinline__ void do_epi(const float (&acc)[2][4][4],
                                       const int* catT, bool diag,
                                       const int (&ci)[2][2],
                                       float (&posm)[2][2], float (&negs)[2][2],
                                       float (&cPos)[4][2], float (&cNeg)[4][2],
                                       int wm, int wn, int l4, int lm) {
    #pragma unroll
    for (int nf = 0; nf < 4; nf++) {
        cPos[nf][0] = cPos[nf][1] = -1e30f;
        cNeg[nf][0] = cNeg[nf][1] = 0.0f;
    }
    #pragma unroll
    for (int nf = 0; nf < 4; nf++) {
        int colL0 = wn * 32 + nf * 8 + lm * 2;
        int cj0 = catT[colL0], cj1 = catT[colL0 + 1];
        #pragma unroll
        for (int mf = 0; mf < 2; mf++) {
            #pragma unroll
            for (int h = 0; h < 2; h++) {
                int rl  = wm * 32 + mf * 16 + h * 8 + l4;
                int cir = ci[mf][h];
                float t0 = fmaf(acc[mf][nf][2 * h + 0], C1, -C2);
                float t1 = fmaf(acc[mf][nf][2 * h + 1], C1, -C2);
                float e0 = ex2f(t0);
                float e1 = ex2f(t1);
                if (cir != cj0)                   negs[mf][h] += e0;
                else if (!diag || rl != colL0)    posm[mf][h] = fmaxf(posm[mf][h], t0);
                if (cir != cj1)                   negs[mf][h] += e1;
                else if (!diag || rl != colL0+1)  posm[mf][h] = fmaxf(posm[mf][h], t1);
                if (cir != cj0) cNeg[nf][0] += e0; else cPos[nf][0] = fmaxf(cPos[nf][0], t0);
                if (cir != cj1) cNeg[nf][1] += e1; else cPos[nf][1] = fmaxf(cPos[nf][1], t1);
            }
        }
    }
}

// ---- col-side cross-thread reduction + global write (non-diag tiles) ----
__device__ __forceinline__ void colside(float (&cPos)[4][2], float (&cNeg)[4][2],
                                        float* sRed, int itP, int jtP,
                                        int wm, int wn, int l4, int lm, int tid) {
    #pragma unroll
    for (int nf = 0; nf < 4; nf++)
        #pragma unroll
        for (int s = 0; s < 2; s++) {
            #pragma unroll
            for (int o = 4; o <= 16; o <<= 1) {
                cPos[nf][s] = fmaxf(cPos[nf][s],
                                    __shfl_xor_sync(0xFFFFFFFFu, cPos[nf][s], o));
                cNeg[nf][s] += __shfl_xor_sync(0xFFFFFFFFu, cNeg[nf][s], o);
            }
        }
    if (l4 == 0) {
        #pragma unroll
        for (int nf = 0; nf < 4; nf++)
            #pragma unroll
            for (int s = 0; s < 2; s++) {
                int col = wn * 32 + nf * 8 + lm * 2 + s;
                sRed[col * 8 + wm]     = cPos[nf][s];
                sRed[col * 8 + 4 + wm] = cNeg[nf][s];
            }
    }
    __syncthreads();
    if (tid < BM) {
        float cp = fmaxf(fmaxf(sRed[tid * 8 + 0], sRed[tid * 8 + 1]),
                         fmaxf(sRed[tid * 8 + 2], sRed[tid * 8 + 3]));
        float cn = sRed[tid * 8 + 4] + sRed[tid * 8 + 5]
                 + sRed[tid * 8 + 6] + sRed[tid * 8 + 7];
        g_pos [itP * BDIM + jtP * BM + tid] = cp * LN2 + M0;
        g_negs[itP * BDIM + jtP * BM + tid] = cn;
    }
}

__device__ __forceinline__ void flush_rows(float* sRed, float (&posm)[2][2],
                                           float (&negs)[2][2],
                                           int wm, int wn, int l4, int lm, int tid,
                                           int curIt, int segC) {
    __syncthreads();
    #pragma unroll
    for (int mf = 0; mf < 2; mf++)
        #pragma unroll
        for (int h = 0; h < 2; h++)
            sRed[(wm * 32 + mf * 16 + h * 8 + l4) * 16 + wn * 4 + lm] = posm[mf][h];
    __syncthreads();
    if (tid < BM) {
        float p = -1e30f;
        #pragma unroll
        for (int x = 0; x < 16; x++) p = fmaxf(p, sRed[tid * 16 + x]);
        g_pos[segC * BDIM + curIt * BM + tid] = p * LN2 + M0;
    }
    __syncthreads();
    #pragma unroll
    for (int mf = 0; mf < 2; mf++)
        #pragma unroll
        for (int h = 0; h < 2; h++)
            sRed[(wm * 32 + mf * 16 + h * 8 + l4) * 16 + wn * 4 + lm] = negs[mf][h];
    __syncthreads();
    if (tid < BM) {
        float s = 0.0f;
        #pragma unroll
        for (int x = 0; x < 16; x++) s += sRed[tid * 16 + x];
        g_negs[segC * BDIM + curIt * BM + tid] = s;
    }
    __syncthreads();
}

// ---------------------------------------------------------------------------
// Kernel 1: L2-normalize + swizzled tile images + scratch identity init.
// ---------------------------------------------------------------------------
__global__ void k_prep(const float* __restrict__ emb) {
    int lane = threadIdx.x & 31;
    int row  = blockIdx.x * 8 + (threadIdx.x >> 5);
    const float4* src = (const float4*)(emb + (size_t)row * DDIM);
    float4 v0 = src[2 * lane];
    float4 v1 = src[2 * lane + 1];
    float ss = v0.x*v0.x + v0.y*v0.y + v0.z*v0.z + v0.w*v0.w
             + v1.x*v1.x + v1.y*v1.y + v1.z*v1.z + v1.w*v1.w;
    #pragma unroll
    for (int o = 16; o; o >>= 1) ss += __shfl_xor_sync(0xFFFFFFFFu, ss, o);
    float inv = 1.0f / fmaxf(sqrtf(ss), 1e-12f);
    __half2 a0 = __floats2half2_rn(v0.x * inv, v0.y * inv);
    __half2 a1 = __floats2half2_rn(v0.z * inv, v0.w * inv);
    __half2 b0 = __floats2half2_rn(v1.x * inv, v1.y * inv);
    __half2 b1 = __floats2half2_rn(v1.z * inv, v1.w * inv);
    uint4 o4;
    o4.x = *reinterpret_cast<uint32_t*>(&a0);
    o4.y = *reinterpret_cast<uint32_t*>(&a1);
    o4.z = *reinterpret_cast<uint32_t*>(&b0);
    o4.w = *reinterpret_cast<uint32_t*>(&b1);
    int rb = row >> 7, r = row & 127;
    int sw = (lane & 24) | ((lane ^ r) & 7);
    *(uint4*)(g_normh + (size_t)rb * TILE_HALF + r * 256 + sw * 8) = o4;

    int i = blockIdx.x * 256 + threadIdx.x;
    if (i < SLOTS / 4) ((float4*)g_pos)[i] = make_float4(-1e30f, -1e30f, -1e30f, -1e30f);
    else               ((float4*)g_negs)[i - SLOTS / 4] = make_float4(0.f, 0.f, 0.f, 0.f);
}

// ---------------------------------------------------------------------------
// Kernel 2: upper-triangle fp16 mma.sync GEMM with DEFERRED epilogue:
// iteration kk issues MMA(kk) and computes epilogue(kk-1) in the same block,
// letting ptxas fill tensor-pipe stall slots with epilogue FMA/MUFU/ALU work.
// ---------------------------------------------------------------------------
__global__ void __launch_bounds__(THREADS, 1)
k_mma(const int* __restrict__ cat) {
    extern __shared__ char smRaw[];
    char* smBase = (char*)((((uintptr_t)smRaw) + 15) & ~(uintptr_t)15);
    const uint32_t base  = smem_u32(smBase);
    const uint32_t aAddr = base + A_OFF;
    const uint32_t bAddr = base + B_OFF;
    const uint32_t mbA   = base + MBAR_OFF;
    const uint32_t mbB0  = base + MBAR_OFF + 8;
    const uint32_t mbB1  = base + MBAR_OFF + 16;
    int*   sCat = (int*)(smBase + CAT_OFF);     // [3][128]
    float* sRed = (float*)(smBase + RED_OFF);

    const int tid  = threadIdx.x;
    const int lane = tid & 31;
    const int warp = tid >> 5;
    const int wm = warp & 3;
    const int wn = warp >> 2;
    const int g  = lane >> 3;
    const int r7 = lane & 7;
    const int l4 = lane >> 2;
    const int lm = lane & 3;

    const int b     = blockIdx.x;
    const int start = b * 14 + min(b, 8);
    const int end   = start + 14 + (b < 8 ? 1 : 0);

    if (tid == 0) { mbar_init(mbA, 1); mbar_init(mbB0, 1); mbar_init(mbB1, 1); }
    __syncthreads();

    uint32_t aRow[2], bRow[2];
    #pragma unroll
    for (int mf = 0; mf < 2; mf++)
        aRow[mf] = aAddr + (uint32_t)(wm * 32 + mf * 16 + (g & 1) * 8 + r7) * 512;
    #pragma unroll
    for (int np = 0; np < 2; np++)
        bRow[np] = (uint32_t)(wn * 32 + np * 16 + (g >> 1) * 8 + r7) * 512;
    const int gh = g >> 1;
    const int gl = g & 1;

    // ---- prologue: tile `start` ----
    int itP, jtP; tile_of(start, itP, jtP);
    if (tid == 0) {
        mbar_expect_tx(mbA, TILEB);
        bulk_cp(aAddr, g_normh + (size_t)itP * TILE_HALF, TILEB, mbA);
        mbar_expect_tx(mbB0, TILEB);
        bulk_cp(bAddr, g_normh + (size_t)jtP * TILE_HALF, TILEB, mbB0);
    }
    if (tid < BM) sCat[tid] = cat[jtP * BM + tid];

    int segC = jtP;
    int   ci[2][2];
    float posm[2][2], negs[2][2];
    #pragma unroll
    for (int mf = 0; mf < 2; mf++)
        #pragma unroll
        for (int h = 0; h < 2; h++) {
            ci[mf][h]   = cat[itP * BM + wm * 32 + mf * 16 + h * 8 + l4];
            posm[mf][h] = -1e30f;
            negs[mf][h] = 0.0f;
        }

    int pA = 1, pB0 = 0, pB1 = 0;
    mbar_wait(mbA, 0);
    __syncthreads();

    float acc0[2][4][4], acc1[2][4][4];

    // ---- peeled iteration kk = start: MMA only (no prev epilogue) ----
    if (start + 1 < end) {
        int itN, jtN; tile_of(start + 1, itN, jtN);
        if (tid == 0) {
            mbar_expect_tx(mbB1, TILEB);
            bulk_cp(bAddr + TILEB, g_normh + (size_t)jtN * TILE_HALF, TILEB, mbB1);
        }
        if (tid < BM) sCat[BM + tid] = cat[jtN * BM + tid];
    }
    mbar_wait(mbB0, pB0); pB0 ^= 1;
    do_mma(acc0, aRow, bAddr, bRow, gh, gl, r7);
    __syncthreads();

    // ---- main loop: MMA(kk) + deferred epilogue(kk-1) ----
    for (int kk = start + 1; kk < end; kk++) {
        const int ph = (kk - start) & 1;
        int itC, jtC; tile_of(kk, itC, jtC);
        const bool aChange = (itC != itP);
        const bool hasNext = (kk + 1 < end);
        int itN = 0, jtN = 0;
        if (hasNext) tile_of(kk + 1, itN, jtN);

        if (tid == 0) {
            if (aChange) {
                mbar_expect_tx(mbA, TILEB);
                bulk_cp(aAddr, g_normh + (size_t)itC * TILE_HALF, TILEB, mbA);
            }
            if (hasNext) {
                uint32_t mb = ph ? mbB0 : mbB1;   // buffer for kk+1 is ph^1
                mbar_expect_tx(mb, TILEB);
                bulk_cp(bAddr + (ph ^ 1) * TILEB,
                        g_normh + (size_t)jtN * TILE_HALF, TILEB, mb);
            }
        }
        if (hasNext && tid < BM)
            sCat[((kk + 1 - start) % 3) * BM + tid] = cat[jtN * BM + tid];

        if (aChange) { mbar_wait(mbA, pA); pA ^= 1; }
        if (ph) { mbar_wait(mbB1, pB1); pB1 ^= 1; }
        else    { mbar_wait(mbB0, pB0); pB0 ^= 1; }

        const int* catP = sCat + ((kk - 1 - start) % 3) * BM;
        const bool diagP = (itP == jtP);
        float cPos[4][2], cNeg[4][2];
        if (ph) {
            do_mma(acc1, aRow, bAddr + TILEB, bRow, gh, gl, r7);
            do_epi(acc0, catP, diagP, ci, posm, negs, cPos, cNeg, wm, wn, l4, lm);
        } else {
            do_mma(acc0, aRow, bAddr, bRow, gh, gl, r7);
            do_epi(acc1, catP, diagP, ci, posm, negs, cPos, cNeg, wm, wn, l4, lm);
        }
        if (!diagP) colside(cPos, cNeg, sRed, itP, jtP, wm, wn, l4, lm, tid);

        if (aChange) {
            flush_rows(sRed, posm, negs, wm, wn, l4, lm, tid, itP, segC);
            segC = jtC;
            #pragma unroll
            for (int mf = 0; mf < 2; mf++)
                #pragma unroll
                for (int h = 0; h < 2; h++) {
                    ci[mf][h]   = cat[itC * BM + wm * 32 + mf * 16 + h * 8 + l4];
                    posm[mf][h] = -1e30f;
                    negs[mf][h] = 0.0f;
                }
        }
        __syncthreads();    // release B[ph^1] + sCat write buffer for next iteration
        itP = itC; jtP = jtC;
    }

    // ---- final deferred epilogue: tile end-1 ----
    {
        const int ph = (end - 1 - start) & 1;
        const int* catP = sCat + ((end - 1 - start) % 3) * BM;
        const bool diagP = (itP == jtP);
        float cPos[4][2], cNeg[4][2];
        if (ph) do_epi(acc1, catP, diagP, ci, posm, negs, cPos, cNeg, wm, wn, l4, lm);
        else    do_epi(acc0, catP, diagP, ci, posm, negs, cPos, cNeg, wm, wn, l4, lm);
        if (!diagP) colside(cPos, cNeg, sRed, itP, jtP, wm, wn, l4, lm, tid);
        flush_rows(sRed, posm, negs, wm, wn, l4, lm, tid, itP, segC);
    }
}

// ---------------------------------------------------------------------------
// Kernel 3: merge 64 slots per row -> per-row loss -> final mean (last block).
// 512 blocks x 256 threads; block owns 16 rows; 16 partials x 4 slots per row.
// ---------------------------------------------------------------------------
__global__ void k_merge(float* __restrict__ out) {
    int tid  = threadIdx.x;
    int row  = tid & 15;
    int part = tid >> 4;                     // 0..15
    int r = blockIdx.x * 16 + row;
    float pm = -1e30f, ns = 0.0f;
    #pragma unroll
    for (int c = part * 4; c < part * 4 + 4; c++) {
        pm = fmaxf(pm, g_pos[c * BDIM + r]);
        ns += g_negs[c * BDIM + r];
    }
    __shared__ float sp[256], sn[256];
    sp[tid] = pm; sn[tid] = ns;
    __syncthreads();
    if (tid < 16) {
        float p = -1e30f, n = 0.0f;
        #pragma unroll
        for (int x = 0; x < 16; x++) {
            p = fmaxf(p, sp[x * 16 + tid]);
            n += sn[x * 16 + tid];
        }
        float loss = 0.0f, cnt = 0.0f;
        if (p > -1e29f && n > 0.0f) {
            float lse = M0 + logf(expf(p - M0) + n);
            loss = lse - p;
            cnt  = 1.0f;
        }
        #pragma unroll
        for (int o = 8; o; o >>= 1) {
            loss += __shfl_xor_sync(0x0000FFFFu, loss, o);
            cnt  += __shfl_xor_sync(0x0000FFFFu, cnt,  o);
        }
        if (tid == 0) { g_psum[blockIdx.x] = loss; g_pcnt[blockIdx.x] = cnt; }
    }
    __threadfence();
    __shared__ int isLast;
    if (tid == 0) isLast = (atomicAdd(&g_sem, 1) == MERGE_BLKS - 1);
    __syncthreads();
    if (isLast) {
        float s = 0.0f, c = 0.0f;
        for (int i = tid; i < MERGE_BLKS; i += 256) {
            s += __ldcg(&g_psum[i]);
            c += __ldcg(&g_pcnt[i]);
        }
        __shared__ float ss[256], sc[256];
        ss[tid] = s; sc[tid] = c;
        __syncthreads();
        for (int o = 128; o; o >>= 1) {
            if (tid < o) { ss[tid] += ss[tid + o]; sc[tid] += sc[tid + o]; }
            __syncthreads();
        }
        if (tid == 0) {
            out[0] = (sc[0] > 0.0f) ? (ss[0] / sc[0]) : 0.0f;
            g_sem = 0;
        }
    }
}

// ---------------------------------------------------------------------------
extern "C" void kernel_launch(void* const* d_in, const int* in_sizes, int n_in,
                              void* d_out, int out_size) {
    const float* emb = (const float*)d_in[0];
    const int*   cat = (const int*)d_in[1];
    // d_in[2] = font_labels, unused

    cudaFuncSetAttribute(k_mma, cudaFuncAttributeMaxDynamicSharedMemorySize, SMEM_NEED);

    k_prep<<<BDIM / 8, 256>>>(emb);
    k_mma<<<GRID_MMA, THREADS, SMEM_NEED>>>(cat);
    k_merge<<<MERGE_BLKS, 256>>>((float*)d_out);
}

// round 14
// speedup vs baseline: 1.0244x; 1.0244x over previous
#include <cuda_runtime.h>
#include <cuda_fp16.h>
#include <cstdint>

// B=8192, D=256, categories int32 on the wire.
#define BDIM 8192
#define DDIM 256
#define INV_T 1.4285714285714286f
#define M0    1.4285714285714286f
#define C1    2.0609929155f          // INV_T * log2(e)
#define C2    2.0609929155f          // M0 * log2(e)
#define LN2   0.69314718056f

#define BM 128
#define NBLK 64
#define THREADS 512                  // 16 warps: 4 in M x 4 in N
#define GRID_MMA 148

#define TILEB 65536                  // 128 rows x 512 B (XOR-swizzled tile image)
#define TILE_HALF 32768
#define A_OFF   0
#define B_OFF   TILEB                // two B buffers follow A
#define CAT_OFF (3 * TILEB)          // int[2][128]
#define RED_OFF (CAT_OFF + 1024)     // 8 KB (two 4KB col-side halves / flush scratch)
#define MBAR_OFF (RED_OFF + 8192)
#define SMEM_NEED (MBAR_OFF + 64)

#define SLOTS (NBLK * BDIM)          // 524288 floats per scratch array
#define MERGE_BLKS 512

__device__ __half g_normh[BDIM * DDIM];
__device__ float  g_pos [SLOTS];
__device__ float  g_negs[SLOTS];
__device__ float  g_psum[MERGE_BLKS];
__device__ float  g_pcnt[MERGE_BLKS];
__device__ int    g_sem;             // zero-init; self-resetting

// ---------------- helpers ----------------
__device__ __forceinline__ uint32_t smem_u32(const void* p) {
    uint32_t a;
    asm("{ .reg .u64 t; cvta.to.shared.u64 t, %1; cvt.u32.u64 %0, t; }" : "=r"(a) : "l"(p));
    return a;
}
__device__ __forceinline__ float ex2f(float x) {
    float y;
    asm("ex2.approx.ftz.f32 %0, %1;" : "=f"(y) : "f"(x));
    return y;
}
__device__ __forceinline__ void mbar_init(uint32_t mbar, uint32_t cnt) {
    asm volatile("mbarrier.init.shared.b64 [%0], %1;" :: "r"(mbar), "r"(cnt) : "memory");
}
__device__ __forceinline__ void mbar_expect_tx(uint32_t mbar, uint32_t bytes) {
    asm volatile("mbarrier.arrive.expect_tx.shared.b64 _, [%0], %1;"
                 :: "r"(mbar), "r"(bytes) : "memory");
}
__device__ __forceinline__ void mbar_wait(uint32_t mbar, uint32_t parity) {
    asm volatile(
        "{\n\t.reg .pred P;\n\t"
        "WL_%=:\n\t"
        "mbarrier.try_wait.parity.acquire.cta.shared::cta.b64 P, [%0], %1, 0x989680;\n\t"
        "@P bra.uni WD_%=;\n\t"
        "bra.uni WL_%=;\n\t"
        "WD_%=:\n\t}"
        :: "r"(mbar), "r"(parity) : "memory");
}
__device__ __forceinline__ void bulk_cp(uint32_t dst, const void* src, uint32_t bytes,
                                        uint32_t mbar) {
    asm volatile(
        "cp.async.bulk.shared::cta.global.mbarrier::complete_tx::bytes [%0], [%1], %2, [%3];"
        :: "r"(dst), "l"(src), "r"(bytes), "r"(mbar) : "memory");
}
__device__ __forceinline__ void ldm4(uint32_t r[4], uint32_t addr) {
    asm volatile("ldmatrix.sync.aligned.m8n8.x4.shared.b16 {%0,%1,%2,%3}, [%4];"
                 : "=r"(r[0]), "=r"(r[1]), "=r"(r[2]), "=r"(r[3]) : "r"(addr));
}
// fp16-ACCUMULATE mma: D (f16x2 pair) = A*B + D. 16 regs of acc per thread total.
__device__ __forceinline__ void mma16816_f16(uint32_t d[2], const uint32_t a[4],
                                             uint32_t b0, uint32_t b1) {
    asm volatile(
        "mma.sync.aligned.m16n8k16.row.col.f16.f16.f16.f16 "
        "{%0,%1},{%2,%3,%4,%5},{%6,%7},{%0,%1};\n"
        : "+r"(d[0]), "+r"(d[1])
        : "r"(a[0]), "r"(a[1]), "r"(a[2]), "r"(a[3]), "r"(b0), "r"(b1));
}
__device__ __forceinline__ void tile_of(int k, int& it, int& jt) {
    int p = k / 65;
    int q = k - p * 65;
    int n1 = NBLK - p;
    if (q < n1) { it = p;            jt = p + q; }
    else        { it = NBLK - 1 - p; jt = (NBLK - 1 - p) + (q - n1); }
}
__device__ __forceinline__ void flush_rows(float* sRed, float posm[2][2], float negs[2][2],
                                           int wm, int wn, int l4, int lm, int tid,
                                           int curIt, int segC) {
    __syncthreads();
    #pragma unroll
    for (int mf = 0; mf < 2; mf++)
        #pragma unroll
        for (int h = 0; h < 2; h++)
            sRed[(wm * 32 + mf * 16 + h * 8 + l4) * 16 + wn * 4 + lm] = posm[mf][h];
    __syncthreads();
    if (tid < BM) {
        float p = -1e30f;
        #pragma unroll
        for (int x = 0; x < 16; x++) p = fmaxf(p, sRed[tid * 16 + x]);
        g_pos[segC * BDIM + curIt * BM + tid] = p * LN2 + M0;   // t -> sim
    }
    __syncthreads();
    #pragma unroll
    for (int mf = 0; mf < 2; mf++)
        #pragma unroll
        for (int h = 0; h < 2; h++)
            sRed[(wm * 32 + mf * 16 + h * 8 + l4) * 16 + wn * 4 + lm] = negs[mf][h];
    __syncthreads();
    if (tid < BM) {
        float s = 0.0f;
        #pragma unroll
        for (int x = 0; x < 16; x++) s += sRed[tid * 16 + x];
        g_negs[segC * BDIM + curIt * BM + tid] = s;
    }
    __syncthreads();
}

// ---------------------------------------------------------------------------
// Kernel 1: L2-normalize + swizzled tile images + scratch identity init.
// ---------------------------------------------------------------------------
__global__ void k_prep(const float* __restrict__ emb) {
    int lane = threadIdx.x & 31;
    int row  = blockIdx.x * 8 + (threadIdx.x >> 5);
    const float4* src = (const float4*)(emb + (size_t)row * DDIM);
    float4 v0 = src[2 * lane];
    float4 v1 = src[2 * lane + 1];
    float ss = v0.x*v0.x + v0.y*v0.y + v0.z*v0.z + v0.w*v0.w
             + v1.x*v1.x + v1.y*v1.y + v1.z*v1.z + v1.w*v1.w;
    #pragma unroll
    for (int o = 16; o; o >>= 1) ss += __shfl_xor_sync(0xFFFFFFFFu, ss, o);
    float inv = 1.0f / fmaxf(sqrtf(ss), 1e-12f);
    __half2 a0 = __floats2half2_rn(v0.x * inv, v0.y * inv);
    __half2 a1 = __floats2half2_rn(v0.z * inv, v0.w * inv);
    __half2 b0 = __floats2half2_rn(v1.x * inv, v1.y * inv);
    __half2 b1 = __floats2half2_rn(v1.z * inv, v1.w * inv);
    uint4 o4;
    o4.x = *reinterpret_cast<uint32_t*>(&a0);
    o4.y = *reinterpret_cast<uint32_t*>(&a1);
    o4.z = *reinterpret_cast<uint32_t*>(&b0);
    o4.w = *reinterpret_cast<uint32_t*>(&b1);
    int rb = row >> 7, r = row & 127;
    int sw = (lane & 24) | ((lane ^ r) & 7);
    *(uint4*)(g_normh + (size_t)rb * TILE_HALF + r * 256 + sw * 8) = o4;

    int i = blockIdx.x * 256 + threadIdx.x;
    if (i < SLOTS / 4) ((float4*)g_pos)[i] = make_float4(-1e30f, -1e30f, -1e30f, -1e30f);
    else               ((float4*)g_negs)[i - SLOTS / 4] = make_float4(0.f, 0.f, 0.f, 0.f);
}

// ---------------------------------------------------------------------------
// Kernel 2: upper-triangle fp16 mma.sync GEMM (fp16 ACCUMULATE), bulk-copied
// tiles, dual-sided fused epilogue. Structure identical to the 71.8us R11.
// ---------------------------------------------------------------------------
__global__ void __launch_bounds__(THREADS, 1)
k_mma(const int* __restrict__ cat) {
    extern __shared__ char smRaw[];
    char* smBase = (char*)((((uintptr_t)smRaw) + 15) & ~(uintptr_t)15);
    const uint32_t base  = smem_u32(smBase);
    const uint32_t aAddr = base + A_OFF;
    const uint32_t bAddr = base + B_OFF;
    const uint32_t mbA   = base + MBAR_OFF;
    const uint32_t mbB0  = base + MBAR_OFF + 8;
    const uint32_t mbB1  = base + MBAR_OFF + 16;
    int*   sCat = (int*)(smBase + CAT_OFF);
    float* sRed = (float*)(smBase + RED_OFF);

    const int tid  = threadIdx.x;
    const int lane = tid & 31;
    const int warp = tid >> 5;
    const int wm = warp & 3;
    const int wn = warp >> 2;
    const int g  = lane >> 3;
    const int r7 = lane & 7;
    const int l4 = lane >> 2;
    const int lm = lane & 3;

    const int b     = blockIdx.x;
    const int start = b * 14 + min(b, 8);
    const int end   = start + 14 + (b < 8 ? 1 : 0);

    if (tid == 0) { mbar_init(mbA, 1); mbar_init(mbB0, 1); mbar_init(mbB1, 1); }
    __syncthreads();

    uint32_t aRow[2], bRow[2];
    #pragma unroll
    for (int mf = 0; mf < 2; mf++)
        aRow[mf] = aAddr + (uint32_t)(wm * 32 + mf * 16 + (g & 1) * 8 + r7) * 512;
    #pragma unroll
    for (int np = 0; np < 2; np++)
        bRow[np] = (uint32_t)(wn * 32 + np * 16 + (g >> 1) * 8 + r7) * 512;
    const int gh = g >> 1;
    const int gl = g & 1;

    int it0, jt0; tile_of(start, it0, jt0);
    if (tid == 0) {
        mbar_expect_tx(mbA, TILEB);
        bulk_cp(aAddr, g_normh + (size_t)it0 * TILE_HALF, TILEB, mbA);
        mbar_expect_tx(mbB0, TILEB);
        bulk_cp(bAddr, g_normh + (size_t)jt0 * TILE_HALF, TILEB, mbB0);
    }
    if (tid < BM) sCat[tid] = cat[jt0 * BM + tid];

    int curIt = it0, segC = jt0;
    int   ci[2][2];
    float posm[2][2], negs[2][2];
    #pragma unroll
    for (int mf = 0; mf < 2; mf++)
        #pragma unroll
        for (int h = 0; h < 2; h++) {
            ci[mf][h]   = cat[curIt * BM + wm * 32 + mf * 16 + h * 8 + l4];
            posm[mf][h] = -1e30f;
            negs[mf][h] = 0.0f;
        }

    mbar_wait(mbA, 0);
    int pA = 1, pB0 = 0, pB1 = 0;
    __syncthreads();

    for (int kk = start; kk < end; kk++) {
        int it, jt; tile_of(kk, it, jt);
        const int cur = (kk - start) & 1;

        if (it != curIt) {
            flush_rows(sRed, posm, negs, wm, wn, l4, lm, tid, curIt, segC);
            if (tid == 0) {
                mbar_expect_tx(mbA, TILEB);
                bulk_cp(aAddr, g_normh + (size_t)it * TILE_HALF, TILEB, mbA);
            }
            __syncthreads();
            mbar_wait(mbA, pA); pA ^= 1;
            curIt = it; segC = jt;
            #pragma unroll
            for (int mf = 0; mf < 2; mf++)
                #pragma unroll
                for (int h = 0; h < 2; h++) {
                    ci[mf][h]   = cat[curIt * BM + wm * 32 + mf * 16 + h * 8 + l4];
                    posm[mf][h] = -1e30f;
                    negs[mf][h] = 0.0f;
                }
        }

        if (kk + 1 < end) {
            int itn, jtn; tile_of(kk + 1, itn, jtn);
            if (tid == 0) {
                uint32_t mb = (cur ^ 1) ? mbB1 : mbB0;
                mbar_expect_tx(mb, TILEB);
                bulk_cp(bAddr + (cur ^ 1) * TILEB, g_normh + (size_t)jtn * TILE_HALF,
                        TILEB, mb);
            }
            if (tid < BM) sCat[(cur ^ 1) * BM + tid] = cat[jtn * BM + tid];
        }

        if (cur == 0) { mbar_wait(mbB0, pB0); pB0 ^= 1; }
        else          { mbar_wait(mbB1, pB1); pB1 ^= 1; }

        // fp16 accumulators: [mf][nf] -> {c0c1, c2c3} packed half2
        uint32_t acc[2][4][2];
        #pragma unroll
        for (int mf = 0; mf < 2; mf++)
            #pragma unroll
            for (int nf = 0; nf < 4; nf++) {
                acc[mf][nf][0] = 0u;
                acc[mf][nf][1] = 0u;
            }

        const uint32_t bBuf = bAddr + cur * TILEB;
        #pragma unroll
        for (int kc = 0; kc < 16; kc++) {
            const int ca = kc * 2 + gh;
            const int cb = kc * 2 + gl;
            const uint32_t swa = (uint32_t)(((ca & 24) | ((ca ^ r7) & 7)) << 4);
            const uint32_t swb = (uint32_t)(((cb & 24) | ((cb ^ r7) & 7)) << 4);
            uint32_t af[2][4], bf[2][4];
            ldm4(af[0], aRow[0] + swa);
            ldm4(af[1], aRow[1] + swa);
            ldm4(bf[0], bBuf + bRow[0] + swb);
            ldm4(bf[1], bBuf + bRow[1] + swb);
            #pragma unroll
            for (int mf = 0; mf < 2; mf++)
                #pragma unroll
                for (int nf = 0; nf < 4; nf++)
                    mma16816_f16(acc[mf][nf], af[mf],
                                 bf[nf >> 1][(nf & 1) * 2], bf[nf >> 1][(nf & 1) * 2 + 1]);
        }

        const bool diag = (it == jt);
        float cPos[4][2], cNeg[4][2];
        #pragma unroll
        for (int nf = 0; nf < 4; nf++) {
            cPos[nf][0] = cPos[nf][1] = -1e30f;
            cNeg[nf][0] = cNeg[nf][1] = 0.0f;
        }
        const int* catT = sCat + cur * BM;
        #pragma unroll
        for (int nf = 0; nf < 4; nf++) {
            int colL0 = wn * 32 + nf * 8 + lm * 2;
            int cj0 = catT[colL0], cj1 = catT[colL0 + 1];
            #pragma unroll
            for (int mf = 0; mf < 2; mf++) {
                #pragma unroll
                for (int h = 0; h < 2; h++) {
                    float2 v = __half22float2(
                        *reinterpret_cast<__half2*>(&acc[mf][nf][h]));
                    int rl  = wm * 32 + mf * 16 + h * 8 + l4;
                    int cir = ci[mf][h];
                    float t0 = fmaf(v.x, C1, -C2);
                    float t1 = fmaf(v.y, C1, -C2);
                    float e0 = ex2f(t0);
                    float e1 = ex2f(t1);
                    if (cir != cj0)                   negs[mf][h] += e0;
                    else if (!diag || rl != colL0)    posm[mf][h] = fmaxf(posm[mf][h], t0);
                    if (cir != cj1)                   negs[mf][h] += e1;
                    else if (!diag || rl != colL0+1)  posm[mf][h] = fmaxf(posm[mf][h], t1);
                    if (cir != cj0) cNeg[nf][0] += e0; else cPos[nf][0] = fmaxf(cPos[nf][0], t0);
                    if (cir != cj1) cNeg[nf][1] += e1; else cPos[nf][1] = fmaxf(cPos[nf][1], t1);
                }
            }
        }

        if (!diag) {
            #pragma unroll
            for (int nf = 0; nf < 4; nf++)
                #pragma unroll
                for (int s = 0; s < 2; s++) {
                    #pragma unroll
                    for (int o = 4; o <= 16; o <<= 1) {
                        cPos[nf][s] = fmaxf(cPos[nf][s],
                                            __shfl_xor_sync(0xFFFFFFFFu, cPos[nf][s], o));
                        cNeg[nf][s] += __shfl_xor_sync(0xFFFFFFFFu, cNeg[nf][s], o);
                    }
                }
            float* sRedC = sRed + cur * 1024;
            if (l4 == 0) {
                #pragma unroll
                for (int nf = 0; nf < 4; nf++)
                    #pragma unroll
                    for (int s = 0; s < 2; s++) {
                        int col = wn * 32 + nf * 8 + lm * 2 + s;
                        sRedC[col * 8 + wm]     = cPos[nf][s];
                        sRedC[col * 8 + 4 + wm] = cNeg[nf][s];
                    }
            }
            __syncthreads();
            if (tid < BM) {
                float cp = fmaxf(fmaxf(sRedC[tid * 8 + 0], sRedC[tid * 8 + 1]),
                                 fmaxf(sRedC[tid * 8 + 2], sRedC[tid * 8 + 3]));
                float cn = sRedC[tid * 8 + 4] + sRedC[tid * 8 + 5]
                         + sRedC[tid * 8 + 6] + sRedC[tid * 8 + 7];
                g_pos [it * BDIM + jt * BM + tid] = cp * LN2 + M0;
                g_negs[it * BDIM + jt * BM + tid] = cn;
            }
        } else {
            __syncthreads();
        }
    }

    flush_rows(sRed, posm, negs, wm, wn, l4, lm, tid, curIt, segC);
}

// ---------------------------------------------------------------------------
// Kernel 3: merge 64 slots per row -> per-row loss -> final mean (last block).
// ---------------------------------------------------------------------------
__global__ void k_merge(float* __restrict__ out) {
    int tid  = threadIdx.x;
    int row  = tid & 15;
    int part = tid >> 4;                     // 0..15
    int r = blockIdx.x * 16 + row;
    float pm = -1e30f, ns = 0.0f;
    #pragma unroll
    for (int c = part * 4; c < part * 4 + 4; c++) {
        pm = fmaxf(pm, g_pos[c * BDIM + r]);
        ns += g_negs[c * BDIM + r];
    }
    __shared__ float sp[256], sn[256];
    sp[tid] = pm; sn[tid] = ns;
    __syncthreads();
    if (tid < 16) {
        float p = -1e30f, n = 0.0f;
        #pragma unroll
        for (int x = 0; x < 16; x++) {
            p = fmaxf(p, sp[x * 16 + tid]);
            n += sn[x * 16 + tid];
        }
        float loss = 0.0f, cnt = 0.0f;
        if (p > -1e29f && n > 0.0f) {
            float lse = M0 + logf(expf(p - M0) + n);
            loss = lse - p;
            cnt  = 1.0f;
        }
        #pragma unroll
        for (int o = 8; o; o >>= 1) {
            loss += __shfl_xor_sync(0x0000FFFFu, loss, o);
            cnt  += __shfl_xor_sync(0x0000FFFFu, cnt,  o);
        }
        if (tid == 0) { g_psum[blockIdx.x] = loss; g_pcnt[blockIdx.x] = cnt; }
    }
    __threadfence();
    __shared__ int isLast;
    if (tid == 0) isLast = (atomicAdd(&g_sem, 1) == MERGE_BLKS - 1);
    __syncthreads();
    if (isLast) {
        float s = 0.0f, c = 0.0f;
        for (int i = tid; i < MERGE_BLKS; i += 256) {
            s += __ldcg(&g_psum[i]);
            c += __ldcg(&g_pcnt[i]);
        }
        __shared__ float ss[256], sc[256];
        ss[tid] = s; sc[tid] = c;
        __syncthreads();
        for (int o = 128; o; o >>= 1) {
            if (tid < o) { ss[tid] += ss[tid + o]; sc[tid] += sc[tid + o]; }
            __syncthreads();
        }
        if (tid == 0) {
            out[0] = (sc[0] > 0.0f) ? (ss[0] / sc[0]) : 0.0f;
            g_sem = 0;
        }
    }
}

// ---------------------------------------------------------------------------
extern "C" void kernel_launch(void* const* d_in, const int* in_sizes, int n_in,
                              void* d_out, int out_size) {
    const float* emb = (const float*)d_in[0];
    const int*   cat = (const int*)d_in[1];
    // d_in[2] = font_labels, unused

    cudaFuncSetAttribute(k_mma, cudaFuncAttributeMaxDynamicSharedMemorySize, SMEM_NEED);

    k_prep<<<BDIM / 8, 256>>>(emb);
    k_mma<<<GRID_MMA, THREADS, SMEM_NEED>>>(cat);
    k_merge<<<MERGE_BLKS, 256>>>((float*)d_out);
}

// round 15
// speedup vs baseline: 1.1504x; 1.1230x over previous
#include <cuda_runtime.h>
#include <cuda_fp16.h>
#include <cstdint>

// B=8192, D=256, categories int32 on the wire.
#define BDIM 8192
#define DDIM 256
#define INV_T 1.4285714285714286f
#define M0    1.4285714285714286f
#define C1    2.0609929155f          // INV_T * log2(e)
#define C2    2.0609929155f          // M0 * log2(e)
#define LN2   0.69314718056f
#define PSH   100.0f                 // sentinel shift: stored pos = sim + 100; 0 = empty

#define BM 128
#define NBLK 64
#define THREADS 256                  // 8 warps: 2 in M (64 rows) x 4 in N (32 cols)
#define GRID_MMA 148

#define TILEB 65536                  // 128 rows x 512 B (XOR-swizzled tile image)
#define TILE_HALF 32768
#define A_OFF   0
#define B_OFF   TILEB                // two B buffers follow A
#define CAT_OFF (3 * TILEB)          // int[2][128]
#define RED_OFF (CAT_OFF + 1024)     // 8 KB (two 4KB halves: col-side / flush scratch)
#define MBAR_OFF (RED_OFF + 8192)
#define SMEM_NEED (MBAR_OFF + 64)

#define SLOTS (NBLK * BDIM)
#define MERGE_BLKS 512

__device__ __half g_normh[BDIM * DDIM];
__device__ float  g_pos [SLOTS];     // zero-init; 0.0 = empty slot (sentinel encoding)
__device__ float  g_negs[SLOTS];     // zero-init; 0.0 = additive identity
__device__ float  g_psum[MERGE_BLKS];
__device__ float  g_pcnt[MERGE_BLKS];
__device__ int    g_sem;             // zero-init; self-resetting

// ---------------- helpers ----------------
__device__ __forceinline__ uint32_t smem_u32(const void* p) {
    uint32_t a;
    asm("{ .reg .u64 t; cvta.to.shared.u64 t, %1; cvt.u32.u64 %0, t; }" : "=r"(a) : "l"(p));
    return a;
}
__device__ __forceinline__ float ex2f(float x) {
    float y;
    asm("ex2.approx.ftz.f32 %0, %1;" : "=f"(y) : "f"(x));
    return y;
}
__device__ __forceinline__ void mbar_init(uint32_t mbar, uint32_t cnt) {
    asm volatile("mbarrier.init.shared.b64 [%0], %1;" :: "r"(mbar), "r"(cnt) : "memory");
}
__device__ __forceinline__ void mbar_expect_tx(uint32_t mbar, uint32_t bytes) {
    asm volatile("mbarrier.arrive.expect_tx.shared.b64 _, [%0], %1;"
                 :: "r"(mbar), "r"(bytes) : "memory");
}
__device__ __forceinline__ void mbar_wait(uint32_t mbar, uint32_t parity) {
    asm volatile(
        "{\n\t.reg .pred P;\n\t"
        "WL_%=:\n\t"
        "mbarrier.try_wait.parity.acquire.cta.shared::cta.b64 P, [%0], %1, 0x989680;\n\t"
        "@P bra.uni WD_%=;\n\t"
        "bra.uni WL_%=;\n\t"
        "WD_%=:\n\t}"
        :: "r"(mbar), "r"(parity) : "memory");
}
__device__ __forceinline__ void bulk_cp(uint32_t dst, const void* src, uint32_t bytes,
                                        uint32_t mbar) {
    asm volatile(
        "cp.async.bulk.shared::cta.global.mbarrier::complete_tx::bytes [%0], [%1], %2, [%3];"
        :: "r"(dst), "l"(src), "r"(bytes), "r"(mbar) : "memory");
}
__device__ __forceinline__ void ldm4(uint32_t r[4], uint32_t addr) {
    asm volatile("ldmatrix.sync.aligned.m8n8.x4.shared.b16 {%0,%1,%2,%3}, [%4];"
                 : "=r"(r[0]), "=r"(r[1]), "=r"(r[2]), "=r"(r[3]) : "r"(addr));
}
// fp16-accumulate mma (validated R14: rel_err 1.1e-7)
__device__ __forceinline__ void mma16816_f16(uint32_t d[2], const uint32_t a[4],
                                             uint32_t b0, uint32_t b1) {
    asm volatile(
        "mma.sync.aligned.m16n8k16.row.col.f16.f16.f16.f16 "
        "{%0,%1},{%2,%3,%4,%5},{%6,%7},{%0,%1};\n"
        : "+r"(d[0]), "+r"(d[1])
        : "r"(a[0]), "r"(a[1]), "r"(a[2]), "r"(a[3]), "r"(b0), "r"(b1));
}
__device__ __forceinline__ void tile_of(int k, int& it, int& jt) {
    int p = k / 65;
    int q = k - p * 65;
    int n1 = NBLK - p;
    if (q < n1) { it = p;            jt = p + q; }
    else        { it = NBLK - 1 - p; jt = (NBLK - 1 - p) + (q - n1); }
}
// write accumulated row stats (posm in t-space) into slot column segC
__device__ __forceinline__ void flush_rows(float* sRed, float posm[4][2], float negs[4][2],
                                           int wm, int wn, int l4, int lm, int tid,
                                           int curIt, int segC) {
    __syncthreads();
    #pragma unroll
    for (int mf = 0; mf < 4; mf++)
        #pragma unroll
        for (int h = 0; h < 2; h++)
            sRed[(wm * 64 + mf * 16 + h * 8 + l4) * 16 + wn * 4 + lm] = posm[mf][h];
    __syncthreads();
    if (tid < BM) {
        float p = -1e30f;
        #pragma unroll
        for (int x = 0; x < 16; x++) p = fmaxf(p, sRed[tid * 16 + x]);
        g_pos[segC * BDIM + curIt * BM + tid] = p * LN2 + M0 + PSH;  // t -> sim + shift
    }
    __syncthreads();
    #pragma unroll
    for (int mf = 0; mf < 4; mf++)
        #pragma unroll
        for (int h = 0; h < 2; h++)
            sRed[(wm * 64 + mf * 16 + h * 8 + l4) * 16 + wn * 4 + lm] = negs[mf][h];
    __syncthreads();
    if (tid < BM) {
        float s = 0.0f;
        #pragma unroll
        for (int x = 0; x < 16; x++) s += sRed[tid * 16 + x];
        g_negs[segC * BDIM + curIt * BM + tid] = s;
    }
    __syncthreads();
}

// ---------------------------------------------------------------------------
// Kernel 1: L2-normalize + write XOR-swizzled tile images (no scratch init —
// g_pos/g_negs rely on zero-init + sentinel encoding + deterministic rewrites).
// ---------------------------------------------------------------------------
__global__ void k_prep(const float* __restrict__ emb) {
    int lane = threadIdx.x & 31;
    int row  = blockIdx.x * 8 + (threadIdx.x >> 5);
    const float4* src = (const float4*)(emb + (size_t)row * DDIM);
    float4 v0 = src[2 * lane];
    float4 v1 = src[2 * lane + 1];
    float ss = v0.x*v0.x + v0.y*v0.y + v0.z*v0.z + v0.w*v0.w
             + v1.x*v1.x + v1.y*v1.y + v1.z*v1.z + v1.w*v1.w;
    #pragma unroll
    for (int o = 16; o; o >>= 1) ss += __shfl_xor_sync(0xFFFFFFFFu, ss, o);
    float inv = 1.0f / fmaxf(sqrtf(ss), 1e-12f);
    __half2 a0 = __floats2half2_rn(v0.x * inv, v0.y * inv);
    __half2 a1 = __floats2half2_rn(v0.z * inv, v0.w * inv);
    __half2 b0 = __floats2half2_rn(v1.x * inv, v1.y * inv);
    __half2 b1 = __floats2half2_rn(v1.z * inv, v1.w * inv);
    uint4 o4;
    o4.x = *reinterpret_cast<uint32_t*>(&a0);
    o4.y = *reinterpret_cast<uint32_t*>(&a1);
    o4.z = *reinterpret_cast<uint32_t*>(&b0);
    o4.w = *reinterpret_cast<uint32_t*>(&b1);
    int rb = row >> 7, r = row & 127;
    int sw = (lane & 24) | ((lane ^ r) & 7);
    *(uint4*)(g_normh + (size_t)rb * TILE_HALF + r * 256 + sw * 8) = o4;
}

// ---------------------------------------------------------------------------
// Kernel 2: upper-triangle fp16 mma.sync GEMM, 8 warps of 64x32 tiles
// (2M x 4N) — fragment smem traffic 384KB/tile vs 512KB with 32x32 tiles.
// ---------------------------------------------------------------------------
__global__ void __launch_bounds__(THREADS, 1)
k_mma(const int* __restrict__ cat) {
    extern __shared__ char smRaw[];
    char* smBase = (char*)((((uintptr_t)smRaw) + 15) & ~(uintptr_t)15);
    const uint32_t base  = smem_u32(smBase);
    const uint32_t aAddr = base + A_OFF;
    const uint32_t bAddr = base + B_OFF;
    const uint32_t mbA   = base + MBAR_OFF;
    const uint32_t mbB0  = base + MBAR_OFF + 8;
    const uint32_t mbB1  = base + MBAR_OFF + 16;
    int*   sCat = (int*)(smBase + CAT_OFF);
    float* sRed = (float*)(smBase + RED_OFF);

    const int tid  = threadIdx.x;
    const int lane = tid & 31;
    const int warp = tid >> 5;           // 0..7
    const int wm = warp & 1;             // 64-row group
    const int wn = warp >> 1;            // 32-col group
    const int g  = lane >> 3;
    const int r7 = lane & 7;
    const int l4 = lane >> 2;
    const int lm = lane & 3;

    const int b     = blockIdx.x;
    const int start = b * 14 + min(b, 8);
    const int end   = start + 14 + (b < 8 ? 1 : 0);

    if (tid == 0) { mbar_init(mbA, 1); mbar_init(mbB0, 1); mbar_init(mbB1, 1); }
    __syncthreads();

    uint32_t aRow[4], bRow[2];
    #pragma unroll
    for (int mf = 0; mf < 4; mf++)
        aRow[mf] = aAddr + (uint32_t)(wm * 64 + mf * 16 + (g & 1) * 8 + r7) * 512;
    #pragma unroll
    for (int np = 0; np < 2; np++)
        bRow[np] = (uint32_t)(wn * 32 + np * 16 + (g >> 1) * 8 + r7) * 512;
    const int gh = g >> 1;
    const int gl = g & 1;

    int it0, jt0; tile_of(start, it0, jt0);
    if (tid == 0) {
        mbar_expect_tx(mbA, TILEB);
        bulk_cp(aAddr, g_normh + (size_t)it0 * TILE_HALF, TILEB, mbA);
        mbar_expect_tx(mbB0, TILEB);
        bulk_cp(bAddr, g_normh + (size_t)jt0 * TILE_HALF, TILEB, mbB0);
    }
    if (tid < BM) sCat[tid] = cat[jt0 * BM + tid];

    int curIt = it0, segC = jt0;
    int   ci[4][2];
    float posm[4][2], negs[4][2];
    #pragma unroll
    for (int mf = 0; mf < 4; mf++)
        #pragma unroll
        for (int h = 0; h < 2; h++) {
            ci[mf][h]   = cat[curIt * BM + wm * 64 + mf * 16 + h * 8 + l4];
            posm[mf][h] = -1e30f;
            negs[mf][h] = 0.0f;
        }

    mbar_wait(mbA, 0);
    int pA = 1, pB0 = 0, pB1 = 0;
    __syncthreads();

    for (int kk = start; kk < end; kk++) {
        int it, jt; tile_of(kk, it, jt);
        const int cur = (kk - start) & 1;

        if (it != curIt) {
            flush_rows(sRed, posm, negs, wm, wn, l4, lm, tid, curIt, segC);
            if (tid == 0) {
                mbar_expect_tx(mbA, TILEB);
                bulk_cp(aAddr, g_normh + (size_t)it * TILE_HALF, TILEB, mbA);
            }
            __syncthreads();
            mbar_wait(mbA, pA); pA ^= 1;
            curIt = it; segC = jt;
            #pragma unroll
            for (int mf = 0; mf < 4; mf++)
                #pragma unroll
                for (int h = 0; h < 2; h++) {
                    ci[mf][h]   = cat[curIt * BM + wm * 64 + mf * 16 + h * 8 + l4];
                    posm[mf][h] = -1e30f;
                    negs[mf][h] = 0.0f;
                }
        }

        if (kk + 1 < end) {
            int itn, jtn; tile_of(kk + 1, itn, jtn);
            if (tid == 0) {
                uint32_t mb = (cur ^ 1) ? mbB1 : mbB0;
                mbar_expect_tx(mb, TILEB);
                bulk_cp(bAddr + (cur ^ 1) * TILEB, g_normh + (size_t)jtn * TILE_HALF,
                        TILEB, mb);
            }
            if (tid < BM) sCat[(cur ^ 1) * BM + tid] = cat[jtn * BM + tid];
        }

        if (cur == 0) { mbar_wait(mbB0, pB0); pB0 ^= 1; }
        else          { mbar_wait(mbB1, pB1); pB1 ^= 1; }

        // fp16 accumulators: [mf][nf] -> {c0c1, c2c3} packed half2
        uint32_t acc[4][4][2];
        #pragma unroll
        for (int mf = 0; mf < 4; mf++)
            #pragma unroll
            for (int nf = 0; nf < 4; nf++) {
                acc[mf][nf][0] = 0u;
                acc[mf][nf][1] = 0u;
            }

        const uint32_t bBuf = bAddr + cur * TILEB;
        #pragma unroll
        for (int kc = 0; kc < 16; kc++) {
            const int ca = kc * 2 + gh;
            const int cb = kc * 2 + gl;
            const uint32_t swa = (uint32_t)(((ca & 24) | ((ca ^ r7) & 7)) << 4);
            const uint32_t swb = (uint32_t)(((cb & 24) | ((cb ^ r7) & 7)) << 4);
            uint32_t af[4][4], bf[2][4];
            ldm4(af[0], aRow[0] + swa);
            ldm4(af[1], aRow[1] + swa);
            ldm4(af[2], aRow[2] + swa);
            ldm4(af[3], aRow[3] + swa);
            ldm4(bf[0], bBuf + bRow[0] + swb);
            ldm4(bf[1], bBuf + bRow[1] + swb);
            #pragma unroll
            for (int mf = 0; mf < 4; mf++)
                #pragma unroll
                for (int nf = 0; nf < 4; nf++)
                    mma16816_f16(acc[mf][nf], af[mf],
                                 bf[nf >> 1][(nf & 1) * 2], bf[nf >> 1][(nf & 1) * 2 + 1]);
        }

        const bool diag = (it == jt);
        float cPos[4][2], cNeg[4][2];
        #pragma unroll
        for (int nf = 0; nf < 4; nf++) {
            cPos[nf][0] = cPos[nf][1] = -1e30f;
            cNeg[nf][0] = cNeg[nf][1] = 0.0f;
        }
        const int* catT = sCat + cur * BM;
        #pragma unroll
        for (int nf = 0; nf < 4; nf++) {
            int colL0 = wn * 32 + nf * 8 + lm * 2;
            int cj0 = catT[colL0], cj1 = catT[colL0 + 1];
            #pragma unroll
            for (int mf = 0; mf < 4; mf++) {
                #pragma unroll
                for (int h = 0; h < 2; h++) {
                    float2 v = __half22float2(
                        *reinterpret_cast<__half2*>(&acc[mf][nf][h]));
                    int rl  = wm * 64 + mf * 16 + h * 8 + l4;
                    int cir = ci[mf][h];
                    float t0 = fmaf(v.x, C1, -C2);
                    float t1 = fmaf(v.y, C1, -C2);
                    float e0 = ex2f(t0);
                    float e1 = ex2f(t1);
                    if (cir != cj0)                   negs[mf][h] += e0;
                    else if (!diag || rl != colL0)    posm[mf][h] = fmaxf(posm[mf][h], t0);
                    if (cir != cj1)                   negs[mf][h] += e1;
                    else if (!diag || rl != colL0+1)  posm[mf][h] = fmaxf(posm[mf][h], t1);
                    if (cir != cj0) cNeg[nf][0] += e0; else cPos[nf][0] = fmaxf(cPos[nf][0], t0);
                    if (cir != cj1) cNeg[nf][1] += e1; else cPos[nf][1] = fmaxf(cPos[nf][1], t1);
                }
            }
        }

        if (!diag) {
            // reduce col stats over l4 (shfl), then over the 2 wm groups via smem
            #pragma unroll
            for (int nf = 0; nf < 4; nf++)
                #pragma unroll
                for (int s = 0; s < 2; s++) {
                    #pragma unroll
                    for (int o = 4; o <= 16; o <<= 1) {
                        cPos[nf][s] = fmaxf(cPos[nf][s],
                                            __shfl_xor_sync(0xFFFFFFFFu, cPos[nf][s], o));
                        cNeg[nf][s] += __shfl_xor_sync(0xFFFFFFFFu, cNeg[nf][s], o);
                    }
                }
            float* sRedC = sRed + cur * 1024;
            if (l4 == 0) {
                #pragma unroll
                for (int nf = 0; nf < 4; nf++)
                    #pragma unroll
                    for (int s = 0; s < 2; s++) {
                        int col = wn * 32 + nf * 8 + lm * 2 + s;
                        sRedC[col * 4 + wm]     = cPos[nf][s];
                        sRedC[col * 4 + 2 + wm] = cNeg[nf][s];
                    }
            }
            __syncthreads();     // also the release point for B[cur] / sCat[cur]
            if (tid < BM) {
                float cp = fmaxf(sRedC[tid * 4], sRedC[tid * 4 + 1]);
                float cn = sRedC[tid * 4 + 2] + sRedC[tid * 4 + 3];
                g_pos [it * BDIM + jt * BM + tid] = cp * LN2 + M0 + PSH;
                g_negs[it * BDIM + jt * BM + tid] = cn;
            }
        } else {
            __syncthreads();
        }
    }

    flush_rows(sRed, posm, negs, wm, wn, l4, lm, tid, curIt, segC);
}

// ---------------------------------------------------------------------------
// Kernel 3: merge 64 slots per row -> per-row loss -> final mean (last block).
// Sentinel: stored pos = sim + 100; empty slot = 0; valid row iff max > 50.
// ---------------------------------------------------------------------------
__global__ void k_merge(float* __restrict__ out) {
    int tid  = threadIdx.x;
    int row  = tid & 15;
    int part = tid >> 4;                     // 0..15
    int r = blockIdx.x * 16 + row;
    float pm = -1e30f, ns = 0.0f;
    #pragma unroll
    for (int c = part * 4; c < part * 4 + 4; c++) {
        pm = fmaxf(pm, g_pos[c * BDIM + r]);
        ns += g_negs[c * BDIM + r];
    }
    __shared__ float sp[256], sn[256];
    sp[tid] = pm; sn[tid] = ns;
    __syncthreads();
    if (tid < 16) {
        float p = -1e30f, n = 0.0f;
        #pragma unroll
        for (int x = 0; x < 16; x++) {
            p = fmaxf(p, sp[x * 16 + tid]);
            n += sn[x * 16 + tid];
        }
        float loss = 0.0f, cnt = 0.0f;
        if (p > 50.0f && n > 0.0f) {
            float ps = p - PSH;              // un-shift -> hardest positive sim
            float lse = M0 + logf(expf(ps - M0) + n);
            loss = lse - ps;
            cnt  = 1.0f;
        }
        #pragma unroll
        for (int o = 8; o; o >>= 1) {
            loss += __shfl_xor_sync(0x0000FFFFu, loss, o);
            cnt  += __shfl_xor_sync(0x0000FFFFu, cnt,  o);
        }
        if (tid == 0) { g_psum[blockIdx.x] = loss; g_pcnt[blockIdx.x] = cnt; }
    }
    __threadfence();
    __shared__ int isLast;
    if (tid == 0) isLast = (atomicAdd(&g_sem, 1) == MERGE_BLKS - 1);
    __syncthreads();
    if (isLast) {
        float s = 0.0f, c = 0.0f;
        for (int i = tid; i < MERGE_BLKS; i += 256) {
            s += __ldcg(&g_psum[i]);
            c += __ldcg(&g_pcnt[i]);
        }
        __shared__ float ss[256], sc[256];
        ss[tid] = s; sc[tid] = c;
        __syncthreads();
        for (int o = 128; o; o >>= 1) {
            if (tid < o) { ss[tid] += ss[tid + o]; sc[tid] += sc[tid + o]; }
            __syncthreads();
        }
        if (tid == 0) {
            out[0] = (sc[0] > 0.0f) ? (ss[0] / sc[0]) : 0.0f;
            g_sem = 0;
        }
    }
}

// ---------------------------------------------------------------------------
extern "C" void kernel_launch(void* const* d_in, const int* in_sizes, int n_in,
                              void* d_out, int out_size) {
    const float* emb = (const float*)d_in[0];
    const int*   cat = (const int*)d_in[1];
    // d_in[2] = font_labels, unused

    cudaFuncSetAttribute(k_mma, cudaFuncAttributeMaxDynamicSharedMemorySize, SMEM_NEED);

    k_prep<<<BDIM / 8, 256>>>(emb);
    k_mma<<<GRID_MMA, THREADS, SMEM_NEED>>>(cat);
    k_merge<<<MERGE_BLKS, 256>>>((float*)d_out);
}